// round 10
// baseline (speedup 1.0000x reference)
#include <cuda_runtime.h>
#include <stdint.h>

#define TPB 128
#define WARPS_PER_BLK 4
#define NVOX 1000000u
#define RS 36  // smem row stride (floats): conflict-free for both phases

typedef unsigned long long u64;

// ---------------- packed f32x2 helpers (Blackwell) ----------------
__device__ __forceinline__ u64 pk2(float lo, float hi) {
    u64 r;
    asm("mov.b64 %0, {%1, %2};" : "=l"(r) : "f"(lo), "f"(hi));
    return r;
}
__device__ __forceinline__ void unpk2(u64 v, float &lo, float &hi) {
    asm("mov.b64 {%0, %1}, %2;" : "=f"(lo), "=f"(hi) : "l"(v));
}
__device__ __forceinline__ u64 fma2(u64 a, u64 b, u64 c) {
    u64 d;
    asm("fma.rn.f32x2 %0, %1, %2, %3;" : "=l"(d) : "l"(a), "l"(b), "l"(c));
    return d;
}

// ---------------- cp.async 16B ----------------
__device__ __forceinline__ void cp_async16(uint32_t saddr, const void *gptr) {
    asm volatile("cp.async.ca.shared.global [%0], [%1], 16;"
                 :: "r"(saddr), "l"(gptr) : "memory");
}
__device__ __forceinline__ void cp_commit() {
    asm volatile("cp.async.commit_group;" ::: "memory");
}
__device__ __forceinline__ void cp_wait0() {
    asm volatile("cp.async.wait_group 0;" ::: "memory");
}

// ------- threefry2x32, key = jax.random.key(42) -> (k1=0, k2=42) ----------
__device__ __forceinline__ uint32_t tf_bits_partitionable(uint32_t i) {
    uint32_t x0 = 0u, x1 = i;
    const uint32_t ks0 = 0u;
    const uint32_t ks1 = 42u;
    const uint32_t ks2 = 0x1BD11BDAu ^ 0u ^ 42u;
    x0 += ks0; x1 += ks1;
#define TF_R(r) { x0 += x1; x1 = __funnelshift_l(x1, x1, (r)); x1 ^= x0; }
#define TF_G1 TF_R(13) TF_R(15) TF_R(26) TF_R(6)
#define TF_G2 TF_R(17) TF_R(29) TF_R(16) TF_R(24)
    TF_G1 x0 += ks1; x1 += ks2 + 1u;
    TF_G2 x0 += ks2; x1 += ks0 + 2u;
    TF_G1 x0 += ks0; x1 += ks1 + 3u;
    TF_G2 x0 += ks1; x1 += ks2 + 4u;
    TF_G1 x0 += ks2; x1 += ks0 + 5u;
#undef TF_G1
#undef TF_G2
#undef TF_R
    return x0 ^ x1;  // partitionable path: lane0 ^ lane1
}

// bits -> jax.random.normal sample * 1e-6 (SYMEIG_EPS).
// Trimmed vs XLA ErfInv32 (noise-value error << 1% budget):
//  - u = max(LO, fma(F,2,-3)): 2F-3 exact; differs from ref by <= 2^-24
//  - poly arg ws = fma(L, -ln2, -2.5) with L = log2(z); w never materialized
//    on the common path; branch test on L directly (w>=5 <=> L<=-5/ln2).
__device__ __forceinline__ float noise_from_bits(uint32_t bits) {
    const float LO = -0.99999994f;       // nextafter(-1,0)
    const float NLN2 = -0.6931471805599453f;
    float F = __uint_as_float((bits >> 9) | 0x3f800000u);  // [1,2)
    float u = fmaxf(LO, fmaf(F, 2.0f, -3.0f));
    float z = 1.0f - u * u;              // Sterbenz-exact in the tail
    float L = __log2f(z);                // <= 0
    float ws = fmaf(L, NLN2, -2.5f);     // = w - 2.5
    float p1 = fmaf(2.81022636e-08f, ws, 3.43273939e-07f);
    p1 = fmaf(p1, ws, -3.5233877e-06f);
    p1 = fmaf(p1, ws, -4.39150654e-06f);
    p1 = fmaf(p1, ws, 0.00021858087f);
    p1 = fmaf(p1, ws, -0.00125372503f);
    p1 = fmaf(p1, ws, -0.00417768164f);
    p1 = fmaf(p1, ws, 0.246640727f);
    p1 = fmaf(p1, ws, 1.50140941f);
    bool big = (L <= -7.2134752f);       // w >= 5
    if (__any_sync(0xffffffffu, big)) {
        float wb = __fsqrt_rn(NLN2 * L) - 3.0f;
        float p2 = fmaf(-0.000200214257f, wb, 0.000100950558f);
        p2 = fmaf(p2, wb, 0.00134934322f);
        p2 = fmaf(p2, wb, -0.00367342844f);
        p2 = fmaf(p2, wb, 0.00573950773f);
        p2 = fmaf(p2, wb, -0.0076224613f);
        p2 = fmaf(p2, wb, 0.00943887047f);
        p2 = fmaf(p2, wb, 1.00167406f);
        p2 = fmaf(p2, wb, 2.83297682f);
        p1 = big ? p2 : p1;
    }
    return 1.4142135452078743e-06f * (p1 * u);  // 1e-6 * sqrt2 folded
}

// --------- FA from symmetric 3x3 (noise pre-reduced to 6 values) ----------
__device__ __forceinline__ float fa_voxel(float f0, float f1, float f2,
                                          float f3, float f4, float f5,
                                          float n00, float n11, float n22,
                                          float h01, float h02, float h12,
                                          float mind) {
    float a00 = f0 + n00;
    float a11 = f2 + n11;
    float a22 = f5 + n22;
    float a01 = f1 + h01;
    float a02 = f3 + h02;
    float a12 = f4 + h12;

    float q = (a00 + a11 + a22) * (1.0f / 3.0f);
    float m0 = a00 - q, m1 = a11 - q, m2 = a22 - q;
    float off = fmaf(a01, a01, fmaf(a02, a02, a12 * a12));
    float S = fmaf(m0, m0, fmaf(m1, m1, fmaf(m2, m2, 2.0f * off)));
    float fa_fast = __fsqrt_rn(__fdividef(1.5f * S, fmaf(3.0f * q, q, S)));
    float p = __fsqrt_rn(S * (1.0f / 6.0f));
    if (q - 2.0f * p >= mind) return fa_fast;  // lambda_min >= q-2p always

    float det = m0 * fmaf(m1, m2, -a12 * a12)
              - a01 * fmaf(a01, m2, -a12 * a02)
              + a02 * fmaf(a01, a12, -m1 * a02);
    float pinv = __fdividef(1.0f, p);
    float r = 0.5f * det * pinv * pinv * pinv;
    r = fminf(fmaxf(r, -1.0f), 1.0f);  // NaN (p==0) collapses to -1
    float phi = acosf(r) * (1.0f / 3.0f);
    float l3 = fmaf(2.0f * p, __cosf(phi + 2.0943951023931953f), q);  // min
    if (l3 >= mind) return fa_fast;

    float l1 = fmaf(2.0f * p, __cosf(phi), q);  // max
    float l2 = 3.0f * q - l1 - l3;
    l1 = fmaxf(l1, mind);
    l2 = fmaxf(l2, mind);
    l3 = fmaxf(l3, mind);
    float d12 = l1 - l2, d23 = l2 - l3, d31 = l3 - l1;
    float num = 0.5f * fmaf(d12, d12, fmaf(d23, d23, d31 * d31));
    float den = fmaf(l1, l1, fmaf(l2, l2, l3 * l3));
    return __fsqrt_rn(__fdividef(num, den));
}

// ---------------- main kernel ----------------------------------------------
__global__ void __launch_bounds__(TPB, 10)
fa_kernel(const float *__restrict__ dwi, const float *__restrict__ mask,
          const float *__restrict__ Winv, const float *__restrict__ mindp,
          float *__restrict__ out) {
    __shared__ __align__(16) float Wsh[384];
    __shared__ __align__(16) float tile[WARPS_PER_BLK][32 * RS];

    for (int k = threadIdx.x; k < 384; k += TPB)
        Wsh[k] = Winv[k] * 0.6931471805599453f;
    __syncthreads();  // Wsh only; tile is warp-private

    const int warp = threadIdx.x >> 5;
    const int lane = threadIdx.x & 31;
    const unsigned vw = (blockIdx.x * WARPS_PER_BLK + warp) * 32u;
    const unsigned v = vw + (unsigned)lane;
    const bool full = (vw + 32u <= NVOX);  // warp-uniform

    const float mind = __ldg(mindp);
    const float4 *__restrict__ dwi4 = reinterpret_cast<const float4 *>(dwi);
    float *trow = &tile[warp][0];
    const uint32_t trow_sa =
        (uint32_t)__cvta_generic_to_shared(&tile[warp][0]);

    const unsigned g = lane >> 3u, e = lane & 7u;
    const uint32_t sa = trow_sa + g * (RS * 4u) + e * 16u;

    // ---- async-load phase 0 (elems 0..31 of the warp's 32 voxels) ----
    if (full) {
#pragma unroll
        for (int k = 0; k < 8; ++k)
            cp_async16(sa + (unsigned)(k * 4) * (RS * 4u),
                       dwi4 + (size_t)(vw + (unsigned)(k * 4) + g) * 16u + e);
    } else {
#pragma unroll
        for (int k = 0; k < 8; ++k) {
            unsigned gv = min(vw + (unsigned)(k * 4) + g, NVOX - 1u);
            cp_async16(sa + (unsigned)(k * 4) * (RS * 4u),
                       dwi4 + (size_t)gv * 16u + e);
        }
    }
    cp_commit();

    // ---- noise j=0..4 (hides phase-0 latency) ----
    const uint32_t nbase = 9u * v;
    float n00 = noise_from_bits(tf_bits_partitionable(nbase + 0u));
    float n1  = noise_from_bits(tf_bits_partitionable(nbase + 1u));
    float n2  = noise_from_bits(tf_bits_partitionable(nbase + 2u));
    float n3  = noise_from_bits(tf_bits_partitionable(nbase + 3u));
    float n11 = noise_from_bits(tf_bits_partitionable(nbase + 4u));
    float h01 = 0.5f * (n1 + n3);

    cp_wait0();
    __syncwarp();

    // ---- consume phase 0 ----
    u64 acc[6];
#pragma unroll
    for (int i = 0; i < 6; ++i) acc[i] = 0ull;
    const float *myrow = &trow[lane * RS];
#pragma unroll
    for (int jt = 0; jt < 8; ++jt) {
        float4 a = *reinterpret_cast<const float4 *>(&myrow[jt * 4]);
        float l0 = __log2f(fmaxf(a.x, mind));
        float l1 = __log2f(fmaxf(a.y, mind));
        float l2 = __log2f(fmaxf(a.z, mind));
        float l3 = __log2f(fmaxf(a.w, mind));
        u64 l01 = pk2(l0, l1), l23 = pk2(l2, l3);
#pragma unroll
        for (int i = 0; i < 6; ++i) {
            ulonglong2 w =
                *reinterpret_cast<const ulonglong2 *>(&Wsh[i * 64 + jt * 4]);
            acc[i] = fma2(w.x, l01, acc[i]);
            acc[i] = fma2(w.y, l23, acc[i]);
        }
    }
    __syncwarp();  // whole warp done reading phase 0

    // ---- async-load phase 1 into same tile (WAR-safe: LDS long done) ----
    if (full) {
#pragma unroll
        for (int k = 0; k < 8; ++k)
            cp_async16(sa + (unsigned)(k * 4) * (RS * 4u),
                       dwi4 + (size_t)(vw + (unsigned)(k * 4) + g) * 16u + 8u +
                           e);
    } else {
#pragma unroll
        for (int k = 0; k < 8; ++k) {
            unsigned gv = min(vw + (unsigned)(k * 4) + g, NVOX - 1u);
            cp_async16(sa + (unsigned)(k * 4) * (RS * 4u),
                       dwi4 + (size_t)gv * 16u + 8u + e);
        }
    }
    cp_commit();

    // prefetch mask early (hides LDG latency behind noise j=5..8)
    const float mval = __ldg(mask + min(v, NVOX - 1u));

    // ---- noise j=5..8 (hides phase-1 latency) ----
    float n5  = noise_from_bits(tf_bits_partitionable(nbase + 5u));
    float n6  = noise_from_bits(tf_bits_partitionable(nbase + 6u));
    float n7  = noise_from_bits(tf_bits_partitionable(nbase + 7u));
    float n22 = noise_from_bits(tf_bits_partitionable(nbase + 8u));
    float h02 = 0.5f * (n2 + n6);
    float h12 = 0.5f * (n5 + n7);

    cp_wait0();
    __syncwarp();

    // ---- consume phase 1 ----
#pragma unroll
    for (int jt = 0; jt < 8; ++jt) {
        float4 a = *reinterpret_cast<const float4 *>(&myrow[jt * 4]);
        float l0 = __log2f(fmaxf(a.x, mind));
        float l1 = __log2f(fmaxf(a.y, mind));
        float l2 = __log2f(fmaxf(a.z, mind));
        float l3 = __log2f(fmaxf(a.w, mind));
        u64 l01 = pk2(l0, l1), l23 = pk2(l2, l3);
#pragma unroll
        for (int i = 0; i < 6; ++i) {
            ulonglong2 w = *reinterpret_cast<const ulonglong2 *>(
                &Wsh[i * 64 + 32 + jt * 4]);
            acc[i] = fma2(w.x, l01, acc[i]);
            acc[i] = fma2(w.y, l23, acc[i]);
        }
    }

    float f0, f1, f2, f3, f4, f5;
    {
        float x, y;
        unpk2(acc[0], x, y); f0 = x + y;
        unpk2(acc[1], x, y); f1 = x + y;
        unpk2(acc[2], x, y); f2 = x + y;
        unpk2(acc[3], x, y); f3 = x + y;
        unpk2(acc[4], x, y); f4 = x + y;
        unpk2(acc[5], x, y); f5 = x + y;
    }

    if (v < NVOX)
        out[v] = fa_voxel(f0, f1, f2, f3, f4, f5, n00, n11, n22, h01, h02,
                          h12, mind) *
                 mval;
}

extern "C" void kernel_launch(void *const *d_in, const int *in_sizes, int n_in,
                              void *d_out, int out_size) {
    const float *dwi  = (const float *)d_in[0];   // [100,100,100,64]
    const float *mask = (const float *)d_in[1];   // [100,100,100,1]
    const float *winv = (const float *)d_in[2];   // [7,64]
    const float *mind = (const float *)d_in[3];   // scalar
    float *out = (float *)d_out;                  // [100,100,100,1]
    (void)in_sizes; (void)n_in; (void)out_size;

    dim3 grid((NVOX + TPB - 1) / TPB);
    fa_kernel<<<grid, TPB>>>(dwi, mask, winv, mind, out);
}

// round 11
// speedup vs baseline: 1.0247x; 1.0247x over previous
#include <cuda_runtime.h>
#include <stdint.h>

#define TPB 128
#define WARPS_PER_BLK 4
#define NVOX 1000000u
#define RS 36  // smem row stride (floats): conflict-free for both phases

typedef unsigned long long u64;

// ---------------- packed f32x2 helpers (Blackwell) ----------------
__device__ __forceinline__ u64 pk2(float lo, float hi) {
    u64 r;
    asm("mov.b64 %0, {%1, %2};" : "=l"(r) : "f"(lo), "f"(hi));
    return r;
}
__device__ __forceinline__ void unpk2(u64 v, float &lo, float &hi) {
    asm("mov.b64 {%0, %1}, %2;" : "=f"(lo), "=f"(hi) : "l"(v));
}
__device__ __forceinline__ u64 fma2(u64 a, u64 b, u64 c) {
    u64 d;
    asm("fma.rn.f32x2 %0, %1, %2, %3;" : "=l"(d) : "l"(a), "l"(b), "l"(c));
    return d;
}

// ---------------- cp.async 16B ----------------
__device__ __forceinline__ void cp_async16(uint32_t saddr, const void *gptr) {
    asm volatile("cp.async.ca.shared.global [%0], [%1], 16;"
                 :: "r"(saddr), "l"(gptr) : "memory");
}
__device__ __forceinline__ void cp_commit() {
    asm volatile("cp.async.commit_group;" ::: "memory");
}
__device__ __forceinline__ void cp_wait0() {
    asm volatile("cp.async.wait_group 0;" ::: "memory");
}

// ------- threefry2x32, key = jax.random.key(42) -> (k1=0, k2=42) ----------
__device__ __forceinline__ uint32_t tf_bits_partitionable(uint32_t i) {
    uint32_t x0 = 0u, x1 = i;
    const uint32_t ks0 = 0u;
    const uint32_t ks1 = 42u;
    const uint32_t ks2 = 0x1BD11BDAu ^ 0u ^ 42u;
    x0 += ks0; x1 += ks1;
#define TF_R(r) { x0 += x1; x1 = __funnelshift_l(x1, x1, (r)); x1 ^= x0; }
#define TF_G1 TF_R(13) TF_R(15) TF_R(26) TF_R(6)
#define TF_G2 TF_R(17) TF_R(29) TF_R(16) TF_R(24)
    TF_G1 x0 += ks1; x1 += ks2 + 1u;
    TF_G2 x0 += ks2; x1 += ks0 + 2u;
    TF_G1 x0 += ks0; x1 += ks1 + 3u;
    TF_G2 x0 += ks1; x1 += ks2 + 4u;
    TF_G1 x0 += ks2; x1 += ks0 + 5u;
#undef TF_G1
#undef TF_G2
#undef TF_R
    return x0 ^ x1;  // partitionable path: lane0 ^ lane1
}

// bits -> jax.random.normal sample * 1e-6 (SYMEIG_EPS).
// Trimmed vs XLA ErfInv32 (noise-value error << 1% budget):
//  - u = max(LO, fma(F,2,-3)): 2F-3 exact; differs from ref by <= 2^-24
//  - poly arg ws = fma(L, -ln2, -2.5) with L = log2(z); w materialized only
//    in the rare big branch; branch test on L (w>=5 <=> L<=-5/ln2).
__device__ __forceinline__ float noise_from_bits(uint32_t bits) {
    const float LO = -0.99999994f;       // nextafter(-1,0)
    const float NLN2 = -0.6931471805599453f;
    float F = __uint_as_float((bits >> 9) | 0x3f800000u);  // [1,2)
    float u = fmaxf(LO, fmaf(F, 2.0f, -3.0f));
    float z = 1.0f - u * u;              // Sterbenz-exact in the tail
    float L = __log2f(z);                // <= 0
    float ws = fmaf(L, NLN2, -2.5f);     // = w - 2.5
    float p1 = fmaf(2.81022636e-08f, ws, 3.43273939e-07f);
    p1 = fmaf(p1, ws, -3.5233877e-06f);
    p1 = fmaf(p1, ws, -4.39150654e-06f);
    p1 = fmaf(p1, ws, 0.00021858087f);
    p1 = fmaf(p1, ws, -0.00125372503f);
    p1 = fmaf(p1, ws, -0.00417768164f);
    p1 = fmaf(p1, ws, 0.246640727f);
    p1 = fmaf(p1, ws, 1.50140941f);
    bool big = (L <= -7.2134752f);       // w >= 5
    if (__any_sync(0xffffffffu, big)) {
        float wb = __fsqrt_rn(NLN2 * L) - 3.0f;
        float p2 = fmaf(-0.000200214257f, wb, 0.000100950558f);
        p2 = fmaf(p2, wb, 0.00134934322f);
        p2 = fmaf(p2, wb, -0.00367342844f);
        p2 = fmaf(p2, wb, 0.00573950773f);
        p2 = fmaf(p2, wb, -0.0076224613f);
        p2 = fmaf(p2, wb, 0.00943887047f);
        p2 = fmaf(p2, wb, 1.00167406f);
        p2 = fmaf(p2, wb, 2.83297682f);
        p1 = big ? p2 : p1;
    }
    return 1.4142135452078743e-06f * (p1 * u);  // 1e-6 * sqrt2 folded
}

// --------- FA from symmetric 3x3 (noise pre-reduced to 6 values) ----------
__device__ __forceinline__ float fa_voxel(float f0, float f1, float f2,
                                          float f3, float f4, float f5,
                                          float n00, float n11, float n22,
                                          float h01, float h02, float h12,
                                          float mind) {
    float a00 = f0 + n00;
    float a11 = f2 + n11;
    float a22 = f5 + n22;
    float a01 = f1 + h01;
    float a02 = f3 + h02;
    float a12 = f4 + h12;

    float q = (a00 + a11 + a22) * (1.0f / 3.0f);
    float m0 = a00 - q, m1 = a11 - q, m2 = a22 - q;
    float off = fmaf(a01, a01, fmaf(a02, a02, a12 * a12));
    float S = fmaf(m0, m0, fmaf(m1, m1, fmaf(m2, m2, 2.0f * off)));
    float fa_fast = __fsqrt_rn(__fdividef(1.5f * S, fmaf(3.0f * q, q, S)));
    float p = __fsqrt_rn(S * (1.0f / 6.0f));
    if (q - 2.0f * p >= mind) return fa_fast;  // lambda_min >= q-2p always

    float det = m0 * fmaf(m1, m2, -a12 * a12)
              - a01 * fmaf(a01, m2, -a12 * a02)
              + a02 * fmaf(a01, a12, -m1 * a02);
    float pinv = __fdividef(1.0f, p);
    float r = 0.5f * det * pinv * pinv * pinv;
    r = fminf(fmaxf(r, -1.0f), 1.0f);  // NaN (p==0) collapses to -1
    float phi = acosf(r) * (1.0f / 3.0f);
    float l3 = fmaf(2.0f * p, __cosf(phi + 2.0943951023931953f), q);  // min
    if (l3 >= mind) return fa_fast;

    float l1 = fmaf(2.0f * p, __cosf(phi), q);  // max
    float l2 = 3.0f * q - l1 - l3;
    l1 = fmaxf(l1, mind);
    l2 = fmaxf(l2, mind);
    l3 = fmaxf(l3, mind);
    float d12 = l1 - l2, d23 = l2 - l3, d31 = l3 - l1;
    float num = 0.5f * fmaf(d12, d12, fmaf(d23, d23, d31 * d31));
    float den = fmaf(l1, l1, fmaf(l2, l2, l3 * l3));
    return __fsqrt_rn(__fdividef(num, den));
}

// ---------------- main kernel ----------------------------------------------
__global__ void __launch_bounds__(TPB, 9)
fa_kernel(const float *__restrict__ dwi, const float *__restrict__ mask,
          const float *__restrict__ Winv, const float *__restrict__ mindp,
          float *__restrict__ out) {
    __shared__ __align__(16) float Wsh[384];
    __shared__ __align__(16) float tile[WARPS_PER_BLK][32 * RS];

    for (int k = threadIdx.x; k < 384; k += TPB)
        Wsh[k] = Winv[k] * 0.6931471805599453f;
    __syncthreads();  // Wsh only; tile is warp-private

    const int warp = threadIdx.x >> 5;
    const int lane = threadIdx.x & 31;
    const unsigned vw = (blockIdx.x * WARPS_PER_BLK + warp) * 32u;
    const unsigned v = vw + (unsigned)lane;
    const bool full = (vw + 32u <= NVOX);  // warp-uniform

    const float mind = __ldg(mindp);
    const float4 *__restrict__ dwi4 = reinterpret_cast<const float4 *>(dwi);
    float *trow = &tile[warp][0];
    const uint32_t trow_sa =
        (uint32_t)__cvta_generic_to_shared(&tile[warp][0]);

    const unsigned g = lane >> 3u, e = lane & 7u;
    const uint32_t sa = trow_sa + g * (RS * 4u) + e * 16u;

    // ---- async-load phase 0 (elems 0..31 of the warp's 32 voxels) ----
    if (full) {
#pragma unroll
        for (int k = 0; k < 8; ++k)
            cp_async16(sa + (unsigned)(k * 4) * (RS * 4u),
                       dwi4 + (size_t)(vw + (unsigned)(k * 4) + g) * 16u + e);
    } else {
#pragma unroll
        for (int k = 0; k < 8; ++k) {
            unsigned gv = min(vw + (unsigned)(k * 4) + g, NVOX - 1u);
            cp_async16(sa + (unsigned)(k * 4) * (RS * 4u),
                       dwi4 + (size_t)gv * 16u + e);
        }
    }
    cp_commit();

    // ---- noise j=0..4 (hides phase-0 latency) ----
    const uint32_t nbase = 9u * v;
    float n00 = noise_from_bits(tf_bits_partitionable(nbase + 0u));
    float n1  = noise_from_bits(tf_bits_partitionable(nbase + 1u));
    float n2  = noise_from_bits(tf_bits_partitionable(nbase + 2u));
    float n3  = noise_from_bits(tf_bits_partitionable(nbase + 3u));
    float n11 = noise_from_bits(tf_bits_partitionable(nbase + 4u));
    float h01 = 0.5f * (n1 + n3);

    cp_wait0();
    __syncwarp();

    // ---- consume phase 0 ----
    u64 acc[6];
#pragma unroll
    for (int i = 0; i < 6; ++i) acc[i] = 0ull;
    const float *myrow = &trow[lane * RS];
#pragma unroll
    for (int jt = 0; jt < 8; ++jt) {
        float4 a = *reinterpret_cast<const float4 *>(&myrow[jt * 4]);
        float l0 = __log2f(fmaxf(a.x, mind));
        float l1 = __log2f(fmaxf(a.y, mind));
        float l2 = __log2f(fmaxf(a.z, mind));
        float l3 = __log2f(fmaxf(a.w, mind));
        u64 l01 = pk2(l0, l1), l23 = pk2(l2, l3);
#pragma unroll
        for (int i = 0; i < 6; ++i) {
            ulonglong2 w =
                *reinterpret_cast<const ulonglong2 *>(&Wsh[i * 64 + jt * 4]);
            acc[i] = fma2(w.x, l01, acc[i]);
            acc[i] = fma2(w.y, l23, acc[i]);
        }
    }
    __syncwarp();  // whole warp done reading phase 0

    // ---- async-load phase 1 into same tile (WAR-safe: LDS long done) ----
    if (full) {
#pragma unroll
        for (int k = 0; k < 8; ++k)
            cp_async16(sa + (unsigned)(k * 4) * (RS * 4u),
                       dwi4 + (size_t)(vw + (unsigned)(k * 4) + g) * 16u + 8u +
                           e);
    } else {
#pragma unroll
        for (int k = 0; k < 8; ++k) {
            unsigned gv = min(vw + (unsigned)(k * 4) + g, NVOX - 1u);
            cp_async16(sa + (unsigned)(k * 4) * (RS * 4u),
                       dwi4 + (size_t)gv * 16u + 8u + e);
        }
    }
    cp_commit();

    // prefetch mask early (hides LDG latency behind noise j=5..8)
    const float mval = full ? __ldg(mask + v) : __ldg(mask + min(v, NVOX - 1u));

    // ---- noise j=5..8 (hides phase-1 latency) ----
    float n5  = noise_from_bits(tf_bits_partitionable(nbase + 5u));
    float n6  = noise_from_bits(tf_bits_partitionable(nbase + 6u));
    float n7  = noise_from_bits(tf_bits_partitionable(nbase + 7u));
    float n22 = noise_from_bits(tf_bits_partitionable(nbase + 8u));
    float h02 = 0.5f * (n2 + n6);
    float h12 = 0.5f * (n5 + n7);

    cp_wait0();
    __syncwarp();

    // ---- consume phase 1 ----
#pragma unroll
    for (int jt = 0; jt < 8; ++jt) {
        float4 a = *reinterpret_cast<const float4 *>(&myrow[jt * 4]);
        float l0 = __log2f(fmaxf(a.x, mind));
        float l1 = __log2f(fmaxf(a.y, mind));
        float l2 = __log2f(fmaxf(a.z, mind));
        float l3 = __log2f(fmaxf(a.w, mind));
        u64 l01 = pk2(l0, l1), l23 = pk2(l2, l3);
#pragma unroll
        for (int i = 0; i < 6; ++i) {
            ulonglong2 w = *reinterpret_cast<const ulonglong2 *>(
                &Wsh[i * 64 + 32 + jt * 4]);
            acc[i] = fma2(w.x, l01, acc[i]);
            acc[i] = fma2(w.y, l23, acc[i]);
        }
    }

    float f0, f1, f2, f3, f4, f5;
    {
        float x, y;
        unpk2(acc[0], x, y); f0 = x + y;
        unpk2(acc[1], x, y); f1 = x + y;
        unpk2(acc[2], x, y); f2 = x + y;
        unpk2(acc[3], x, y); f3 = x + y;
        unpk2(acc[4], x, y); f4 = x + y;
        unpk2(acc[5], x, y); f5 = x + y;
    }

    if (v < NVOX)
        out[v] = fa_voxel(f0, f1, f2, f3, f4, f5, n00, n11, n22, h01, h02,
                          h12, mind) *
                 mval;
}

extern "C" void kernel_launch(void *const *d_in, const int *in_sizes, int n_in,
                              void *d_out, int out_size) {
    const float *dwi  = (const float *)d_in[0];   // [100,100,100,64]
    const float *mask = (const float *)d_in[1];   // [100,100,100,1]
    const float *winv = (const float *)d_in[2];   // [7,64]
    const float *mind = (const float *)d_in[3];   // scalar
    float *out = (float *)d_out;                  // [100,100,100,1]
    (void)in_sizes; (void)n_in; (void)out_size;

    dim3 grid((NVOX + TPB - 1) / TPB);
    fa_kernel<<<grid, TPB>>>(dwi, mask, winv, mind, out);
}